// round 12
// baseline (speedup 1.0000x reference)
#include <cuda_runtime.h>
#include <cuda_bf16.h>
#include <math.h>
#include <stdint.h>

// ---------------------------------------------------------------------------
// ChannelBlock: B=32, N=784 (28x28), C=384, heads=8, hd=48, MLP hidden=1536
// bf16 mma.sync GEMMs (R8 config), tiled cpe_ln, float4-tiled attnA
// (occupancy-capped, float4 LDG), fused softmax+attnB (R10).
// ---------------------------------------------------------------------------

#define Bsz   32
#define Ntok  784
#define Cdim  384
#define NT    (Bsz * Ntok)     // 25088
#define H3    (3 * Cdim)       // 1152
#define HID   1536
#define NH    8
#define HD    48
#define NCHUNK 7               // attnA token chunks (112 each)

typedef __nv_bfloat16 bf16;

// scratch (static device memory; no allocation anywhere)
__device__ float g_xa  [(size_t)NT * Cdim];
__device__ bf16  g_ln  [(size_t)NT * Cdim];
__device__ float g_qkv [(size_t)NT * H3];
__device__ float g_attn[(size_t)NCHUNK * Bsz * NH * HD * HD];  // partial logits
__device__ bf16  g_att [(size_t)NT * Cdim];
__device__ float g_xb  [(size_t)NT * Cdim];
__device__ bf16  g_h   [(size_t)NT * HID];
// bf16 weights: qkv | proj | fc1 | fc2
#define W_QKV 0
#define W_PROJ (H3 * Cdim)
#define W_FC1  (W_PROJ + Cdim * Cdim)
#define W_FC2  (W_FC1 + HID * Cdim)
#define W_TOT  (W_FC2 + Cdim * HID)
__device__ bf16  g_wbf [(size_t)W_TOT];

// single launch: convert all 4 weight matrices to bf16
__global__ void cvt_all_kernel(const float* __restrict__ qkv_w,
                               const float* __restrict__ proj_w,
                               const float* __restrict__ fc1_w,
                               const float* __restrict__ fc2_w,
                               bf16* __restrict__ out)
{
    int i = blockIdx.x * blockDim.x + threadIdx.x;
    if (i >= W_TOT) return;
    float v;
    if (i < W_PROJ)      v = qkv_w[i];
    else if (i < W_FC1)  v = proj_w[i - W_PROJ];
    else if (i < W_FC2)  v = fc1_w[i - W_FC1];
    else                 v = fc2_w[i - W_FC2];
    out[i] = __float2bfloat16(v);
}

// ---------------------------------------------------------------------------
// Tiled fused cpe + LN (R8).
// ---------------------------------------------------------------------------
#define TJ 7
__global__ __launch_bounds__(Cdim)
void cpe_ln_kernel(const float* __restrict__ x,
                   const float* __restrict__ w,
                   const float* __restrict__ bias,
                   const float* __restrict__ lng,
                   const float* __restrict__ lnb,
                   float* __restrict__ y,
                   bf16* __restrict__ yln)
{
    __shared__ float tile[3][TJ + 2][Cdim];
    __shared__ float redS[12][TJ], redQ[12][TJ];
    __shared__ float stats[TJ][2];

    int c  = threadIdx.x;
    int jg = blockIdx.x;
    int i  = blockIdx.y;
    int b  = blockIdx.z;
    int j0 = jg * TJ;

    const float* xb = x + (size_t)b * Ntok * Cdim;

#pragma unroll
    for (int s = 0; s < 3 * (TJ + 2); s++) {
        int ri = s / (TJ + 2) + i - 1;
        int cj = s % (TJ + 2) + j0 - 1;
        float v = 0.f;
        if (ri >= 0 && ri < 28 && cj >= 0 && cj < 28)
            v = xb[(size_t)(ri * 28 + cj) * Cdim + c];
        tile[s / (TJ + 2)][s % (TJ + 2)][c] = v;
    }
    __syncthreads();

    const float* wc = w + c * 9;
    float wr[9];
#pragma unroll
    for (int q = 0; q < 9; q++) wr[q] = wc[q];
    float bs = bias[c];

    float val[TJ];
#pragma unroll
    for (int jt = 0; jt < TJ; jt++) {
        float acc = bs;
#pragma unroll
        for (int di = 0; di < 3; di++)
#pragma unroll
            for (int dj = 0; dj < 3; dj++)
                acc += wr[di * 3 + dj] * tile[di][jt + dj][c];
        val[jt] = tile[1][1 + jt][c] + acc;
    }

    int warp = c >> 5, lane = c & 31;
#pragma unroll
    for (int jt = 0; jt < TJ; jt++) {
        float s = val[jt], q = val[jt] * val[jt];
#pragma unroll
        for (int o = 16; o; o >>= 1) {
            s += __shfl_xor_sync(0xffffffffu, s, o);
            q += __shfl_xor_sync(0xffffffffu, q, o);
        }
        if (lane == 0) { redS[warp][jt] = s; redQ[warp][jt] = q; }
    }
    __syncthreads();
    if (c < TJ) {
        float ts = 0.f, tq = 0.f;
#pragma unroll
        for (int k = 0; k < 12; k++) { ts += redS[k][c]; tq += redQ[k][c]; }
        float mean = ts * (1.f / Cdim);
        float var  = tq * (1.f / Cdim) - mean * mean;
        stats[c][0] = mean;
        stats[c][1] = rsqrtf(var + 1e-5f);
    }
    __syncthreads();

    float gg = lng[c], bb = lnb[c];
#pragma unroll
    for (int jt = 0; jt < TJ; jt++) {
        size_t idx = ((size_t)b * Ntok + i * 28 + j0 + jt) * Cdim + c;
        float v = val[jt];
        y[idx] = v;
        yln[idx] = __float2bfloat16((v - stats[jt][0]) * stats[jt][1] * gg + bb);
    }
}

// ---------------------------------------------------------------------------
// bf16 GEMM (R8 config: best measured).
// ---------------------------------------------------------------------------
#define BM 128
#define BN 128
#define BK 32
#define STAGES 3
#define ASTG (BM * 64)
#define STG_BYTES (2 * ASTG)

__device__ __forceinline__ void cp16(unsigned saddr, const void* g)
{
    asm volatile("cp.async.cg.shared.global [%0], [%1], 16;\n" :: "r"(saddr), "l"(g));
}
__device__ __forceinline__ void ldsm4(uint32_t& r0, uint32_t& r1, uint32_t& r2,
                                      uint32_t& r3, uint32_t a)
{
    asm volatile("ldmatrix.sync.aligned.m8n8.x4.shared.b16 {%0,%1,%2,%3}, [%4];"
                 : "=r"(r0), "=r"(r1), "=r"(r2), "=r"(r3) : "r"(a));
}

template<int EPI, int K>
__global__ __launch_bounds__(256, 2)
void gemm_bf16(const bf16* __restrict__ A, const bf16* __restrict__ W,
               const float* __restrict__ bias, const float* __restrict__ res,
               void* __restrict__ Cout, int M, int N)
{
    __shared__ alignas(128) char sm[STAGES * STG_BYTES];
    uint32_t sb = (uint32_t)__cvta_generic_to_shared(sm);

    int tid = threadIdx.x;
    int w = tid >> 5, l = tid & 31;
    int row0 = blockIdx.y * BM;
    int col0 = blockIdx.x * BN;
    int wm = (w & 1) * 64;
    int wn = (w >> 1) * 32;
    int g = l >> 2, t = l & 3;

    int jj  = l >> 3;
    int rlo = l & 7;
    int rowA_in = (jj & 1) * 8 + rlo;
    int cA = jj >> 1;
    uint32_t aoff[4], axr[4];
#pragma unroll
    for (int mi = 0; mi < 4; mi++) {
        int rA = wm + mi * 16 + rowA_in;
        aoff[mi] = (uint32_t)rA * 64;
        axr[mi]  = (uint32_t)(((rA >> 1) & 3) << 4);
    }
    int rowB_in = (jj >> 1) * 8 + rlo;
    int cB = jj & 1;
    uint32_t boff[2], bxr[2];
#pragma unroll
    for (int p = 0; p < 2; p++) {
        int rB = wn + p * 16 + rowB_in;
        boff[p] = (uint32_t)(ASTG + rB * 64);
        bxr[p]  = (uint32_t)(((rB >> 1) & 3) << 4);
    }

    float acc[4][4][4];
#pragma unroll
    for (int mi = 0; mi < 4; mi++)
#pragma unroll
        for (int ni = 0; ni < 4; ni++)
#pragma unroll
            for (int r = 0; r < 4; r++) acc[mi][ni][r] = 0.f;

    constexpr int NS = K / BK;

    auto load_stage = [&](int s) {
        uint32_t tb = sb + (s % STAGES) * STG_BYTES;
        int kt = s * BK;
        const bf16* Ab = A + (size_t)row0 * K + kt;
        const bf16* Wb = W + (size_t)col0 * K + kt;
#pragma unroll
        for (int i = 0; i < 2; i++) {
            int id = tid + i * 256;
            int r = id >> 2, c = id & 3;
            int cs = c ^ ((r >> 1) & 3);
            cp16(tb + r * 64 + cs * 16, Ab + (size_t)r * K + c * 8);
            cp16(tb + ASTG + r * 64 + cs * 16, Wb + (size_t)r * K + c * 8);
        }
    };

    load_stage(0);
    asm volatile("cp.async.commit_group;\n");
    load_stage(1);
    asm volatile("cp.async.commit_group;\n");

#pragma unroll
    for (int s = 0; s < NS; s++) {
        asm volatile("cp.async.wait_group 1;\n");
        __syncthreads();

        if (s + STAGES - 1 < NS) load_stage(s + STAGES - 1);
        asm volatile("cp.async.commit_group;\n");

        uint32_t stb = sb + (s % STAGES) * STG_BYTES;
#pragma unroll
        for (int kk = 0; kk < 2; kk++) {
            uint32_t c0 = kk * 2;
            uint32_t af[4][4], bq[2][4];
#pragma unroll
            for (int mi = 0; mi < 4; mi++)
                ldsm4(af[mi][0], af[mi][1], af[mi][2], af[mi][3],
                      stb + aoff[mi] + ((((c0 + cA) << 4)) ^ axr[mi]));
#pragma unroll
            for (int p = 0; p < 2; p++)
                ldsm4(bq[p][0], bq[p][1], bq[p][2], bq[p][3],
                      stb + boff[p] + ((((c0 + cB) << 4)) ^ bxr[p]));

#pragma unroll
            for (int mi = 0; mi < 4; mi++)
#pragma unroll
                for (int ni = 0; ni < 4; ni++) {
                    int p = ni >> 1, q = ni & 1;
                    asm volatile(
                        "mma.sync.aligned.m16n8k16.row.col.f32.bf16.bf16.f32 "
                        "{%0,%1,%2,%3}, {%4,%5,%6,%7}, {%8,%9}, {%0,%1,%2,%3};"
                        : "+f"(acc[mi][ni][0]), "+f"(acc[mi][ni][1]),
                          "+f"(acc[mi][ni][2]), "+f"(acc[mi][ni][3])
                        : "r"(af[mi][0]), "r"(af[mi][1]), "r"(af[mi][2]), "r"(af[mi][3]),
                          "r"(bq[p][2 * q]), "r"(bq[p][2 * q + 1]));
                }
        }
    }

#pragma unroll
    for (int mi = 0; mi < 4; mi++) {
#pragma unroll
        for (int ni = 0; ni < 4; ni++) {
            int col = col0 + wn + ni * 8 + 2 * t;
#pragma unroll
            for (int half = 0; half < 2; half++) {
                int row = row0 + wm + mi * 16 + g + half * 8;
                size_t idx = (size_t)row * N + col;
                float v0 = acc[mi][ni][2 * half];
                float v1 = acc[mi][ni][2 * half + 1];
                if (EPI == 0) {
                    *(float2*)&((float*)Cout)[idx] = make_float2(v0, v1);
                } else if (EPI == 2) {
                    float2 bv = *(const float2*)&bias[col];
                    v0 += bv.x; v1 += bv.y;
                    v0 = 0.5f * v0 * (1.f + erff(v0 * 0.7071067811865475f));
                    v1 = 0.5f * v1 * (1.f + erff(v1 * 0.7071067811865475f));
                    __nv_bfloat162 pk;
                    pk.x = __float2bfloat16(v0);
                    pk.y = __float2bfloat16(v1);
                    *(__nv_bfloat162*)&((bf16*)Cout)[idx] = pk;
                } else {
                    float2 bv = *(const float2*)&bias[col];
                    float2 rv = *(const float2*)&res[idx];
                    v0 += bv.x + rv.x; v1 += bv.y + rv.y;
                    *(float2*)&((float*)Cout)[idx] = make_float2(v0, v1);
                }
            }
        }
    }
}

// ---------------------------------------------------------------------------
// Channel attention stage A: per (bh, chunk) partial (k*s)^T v over 112 tokens.
// 144 threads = 12x12 grid of 4x4 thread tiles; float4 LDG + float4 LDS.
// __launch_bounds__(144, 8) caps regs at 56 -> ~56% occupancy.
// Per-output fmaf chain (ascending n) identical to R11 -> bit-identical.
// ---------------------------------------------------------------------------
#define ATHR 144
#define KVS  56    // padded row stride (floats), 16B aligned
__global__ __launch_bounds__(ATHR, 8)
void attnA_partial(const float* __restrict__ qkv, float* __restrict__ partial)
{
    __shared__ float ks[16][KVS];
    __shared__ float vs[16][KVS];

    int bh = blockIdx.x;
    int b = bh >> 3, h = bh & 7;
    int chunk = blockIdx.y;
    int nstart = chunk * 112;
    int tid = threadIdx.x;
    int tx = tid % 12, ty = tid / 12;     // 12 x 12 tile grid
    const float scale = 0.14433756729740643f;   // 48^-0.5

    float acc[4][4];
#pragma unroll
    for (int i = 0; i < 4; i++)
#pragma unroll
        for (int j = 0; j < 4; j++) acc[i][j] = 0.f;

    const float* base = qkv + (size_t)b * Ntok * H3 + h * HD;

    for (int n0 = nstart; n0 < nstart + 112; n0 += 16) {
        // float4 loads: 2 buffers x 16 tokens x 12 float4 = 384 loads
#pragma unroll
        for (int it = 0; it < 3; it++) {
            int idx = tid + it * ATHR;           // 0..431
            if (idx < 384) {
                int buf = idx / 192;             // 0 = k, 1 = v
                int rem = idx - buf * 192;
                int nn = rem / 12, d4 = rem - nn * 12;
                const float* r = base + (size_t)(n0 + nn) * H3
                               + (buf ? 2 * Cdim : Cdim) + d4 * 4;
                float4 v4 = *(const float4*)r;
                if (buf == 0) {
                    v4.x *= scale; v4.y *= scale; v4.z *= scale; v4.w *= scale;
                    *(float4*)&ks[nn][d4 * 4] = v4;
                } else {
                    *(float4*)&vs[nn][d4 * 4] = v4;
                }
            }
        }
        __syncthreads();
#pragma unroll
        for (int nn = 0; nn < 16; nn++) {
            float4 rk = *(const float4*)&ks[nn][ty * 4];
            float4 rv = *(const float4*)&vs[nn][tx * 4];
            float k[4] = {rk.x, rk.y, rk.z, rk.w};
            float v[4] = {rv.x, rv.y, rv.z, rv.w};
#pragma unroll
            for (int i = 0; i < 4; i++)
#pragma unroll
                for (int j = 0; j < 4; j++)
                    acc[i][j] = fmaf(k[i], v[j], acc[i][j]);
        }
        __syncthreads();
    }

    float* o = partial + ((size_t)chunk * (Bsz * NH) + bh) * (HD * HD);
#pragma unroll
    for (int i = 0; i < 4; i++) {
        float4 st = make_float4(acc[i][0], acc[i][1], acc[i][2], acc[i][3]);
        *(float4*)&o[(ty * 4 + i) * HD + tx * 4] = st;
    }
}

// ---------------------------------------------------------------------------
// Fused softmax + attnB (R10). One block per (b,h), 384 threads.
// ---------------------------------------------------------------------------
__global__ __launch_bounds__(384)
void attnBF_kernel(const float* __restrict__ qkv, const float* __restrict__ partial,
                   bf16* __restrict__ out)
{
    __shared__ float at[HD * HD];
    __shared__ float qs[56][HD];

    int bh = blockIdx.x;
    int b = bh >> 3, h = bh & 7;
    int tid = threadIdx.x;

#pragma unroll
    for (int it = 0; it < 6; it++) {
        int idx = tid + it * 384;
        float s = 0.f;
#pragma unroll
        for (int ch = 0; ch < NCHUNK; ch++)
            s += partial[((size_t)ch * (Bsz * NH) + bh) * (HD * HD) + idx];
        at[idx] = s;
    }
    __syncthreads();

    if (tid < HD) {
        float* row = &at[tid * HD];
        float m = -1e30f;
#pragma unroll
        for (int e = 0; e < HD; e++) m = fmaxf(m, row[e]);
        float s = 0.f;
#pragma unroll
        for (int e = 0; e < HD; e++) { float tv = expf(row[e] - m); row[e] = tv; s += tv; }
        float inv = 1.f / s;
#pragma unroll
        for (int e = 0; e < HD; e++) row[e] *= inv;
    }
    __syncthreads();

    int nl = tid / HD;
    int d  = tid - nl * HD;
    float4 arow[12];
#pragma unroll
    for (int e4 = 0; e4 < 12; e4++)
        arow[e4] = *(float4*)&at[d * HD + e4 * 4];

    const float* qb = qkv + (size_t)b * Ntok * H3 + h * HD + d;
    bf16* ob = out + (size_t)b * Ntok * Cdim + h * HD + d;

    for (int n0 = 0; n0 < Ntok; n0 += 56) {
#pragma unroll
        for (int r = 0; r < 7; r++)
            qs[nl + 8 * r][d] = qb[(size_t)(n0 + nl + 8 * r) * H3];
        __syncthreads();

        float acc[7] = {0.f, 0.f, 0.f, 0.f, 0.f, 0.f, 0.f};
#pragma unroll
        for (int e4 = 0; e4 < 12; e4++) {
            float4 ar = arow[e4];
#pragma unroll
            for (int r = 0; r < 7; r++) {
                float4 qv = *(float4*)&qs[nl + 8 * r][e4 * 4];
                acc[r] = fmaf(ar.x, qv.x, acc[r]);
                acc[r] = fmaf(ar.y, qv.y, acc[r]);
                acc[r] = fmaf(ar.z, qv.z, acc[r]);
                acc[r] = fmaf(ar.w, qv.w, acc[r]);
            }
        }
#pragma unroll
        for (int r = 0; r < 7; r++)
            ob[(size_t)(n0 + nl + 8 * r) * Cdim] = __float2bfloat16(acc[r]);
        __syncthreads();
    }
}

// ---------------------------------------------------------------------------
// Launch
// ---------------------------------------------------------------------------
extern "C" void kernel_launch(void* const* d_in, const int* in_sizes, int n_in,
                              void* d_out, int out_size)
{
    const float* x       = (const float*)d_in[0];
    const float* cpe0_w  = (const float*)d_in[3];
    const float* cpe0_b  = (const float*)d_in[4];
    const float* cpe1_w  = (const float*)d_in[5];
    const float* cpe1_b  = (const float*)d_in[6];
    const float* norm1_g = (const float*)d_in[7];
    const float* norm1_b = (const float*)d_in[8];
    const float* qkv_w   = (const float*)d_in[9];
    const float* proj_w  = (const float*)d_in[10];
    const float* proj_b  = (const float*)d_in[11];
    const float* norm2_g = (const float*)d_in[12];
    const float* norm2_b = (const float*)d_in[13];
    const float* fc1_w   = (const float*)d_in[14];
    const float* fc1_b   = (const float*)d_in[15];
    const float* fc2_w   = (const float*)d_in[16];
    const float* fc2_b   = (const float*)d_in[17];
    float* out = (float*)d_out;

    float *xa, *qkvb, *attn, *xb;
    bf16 *ln, *att, *hbuf, *wbf;
    cudaGetSymbolAddress((void**)&xa,    g_xa);
    cudaGetSymbolAddress((void**)&ln,    g_ln);
    cudaGetSymbolAddress((void**)&qkvb,  g_qkv);
    cudaGetSymbolAddress((void**)&attn,  g_attn);
    cudaGetSymbolAddress((void**)&att,   g_att);
    cudaGetSymbolAddress((void**)&xb,    g_xb);
    cudaGetSymbolAddress((void**)&hbuf,  g_h);
    cudaGetSymbolAddress((void**)&wbf,   g_wbf);

    dim3 cpeGrid(4, 28, Bsz);

    // one launch: convert all weights to bf16
    cvt_all_kernel<<<(W_TOT + 255) / 256, 256>>>(qkv_w, proj_w, fc1_w, fc2_w, wbf);

    // xa = cpe0(x); ln = LN1(xa) [bf16]
    cpe_ln_kernel<<<cpeGrid, Cdim>>>(x, cpe0_w, cpe0_b, norm1_g, norm1_b, xa, ln);
    // qkv = ln1 @ qkv_w^T  (fp32 out)
    gemm_bf16<0, Cdim><<<dim3(H3 / BN, NT / BM), 256>>>(ln, wbf + W_QKV, nullptr, nullptr, qkvb, NT, H3);
    // channel attention
    attnA_partial<<<dim3(Bsz * NH, NCHUNK), ATHR>>>(qkvb, attn);
    attnBF_kernel<<<Bsz * NH, 384>>>(qkvb, attn, att);
    // xb = xa + att @ proj_w^T + proj_b  (fp32 out)
    gemm_bf16<3, Cdim><<<dim3(Cdim / BN, NT / BM), 256>>>(att, wbf + W_PROJ, proj_b, xa, xb, NT, Cdim);
    // xc = cpe1(xb) -> xa ; ln = LN2(xc) [bf16]
    cpe_ln_kernel<<<cpeGrid, Cdim>>>(xb, cpe1_w, cpe1_b, norm2_g, norm2_b, xa, ln);
    // h = gelu(ln2 @ fc1^T + b1) [bf16 out]
    gemm_bf16<2, Cdim><<<dim3(HID / BN, NT / BM), 256>>>(ln, wbf + W_FC1, fc1_b, nullptr, hbuf, NT, HID);
    // out = xc + h @ fc2^T + b2 (fp32 out)
    gemm_bf16<3, HID><<<dim3(Cdim / BN, NT / BM), 256>>>(hbuf, wbf + W_FC2, fc2_b, xa, out, NT, Cdim);
}

// round 13
// speedup vs baseline: 1.0045x; 1.0045x over previous
#include <cuda_runtime.h>
#include <cuda_bf16.h>
#include <math.h>
#include <stdint.h>

// ---------------------------------------------------------------------------
// ChannelBlock: B=32, N=784 (28x28), C=384, heads=8, hd=48, MLP hidden=1536
// bf16 mma.sync GEMMs (R8 config), tiled cpe_ln, prefetch-pipelined attnA,
// fused softmax+attnB with 2-way N split.
// ---------------------------------------------------------------------------

#define Bsz   32
#define Ntok  784
#define Cdim  384
#define NT    (Bsz * Ntok)     // 25088
#define H3    (3 * Cdim)       // 1152
#define HID   1536
#define NH    8
#define HD    48
#define NCHUNK 7               // attnA token chunks (112 each)

typedef __nv_bfloat16 bf16;

// scratch (static device memory; no allocation anywhere)
__device__ float g_xa  [(size_t)NT * Cdim];
__device__ bf16  g_ln  [(size_t)NT * Cdim];
__device__ float g_qkv [(size_t)NT * H3];
__device__ float g_attn[(size_t)NCHUNK * Bsz * NH * HD * HD];  // partial logits
__device__ bf16  g_att [(size_t)NT * Cdim];
__device__ float g_xb  [(size_t)NT * Cdim];
__device__ bf16  g_h   [(size_t)NT * HID];
// bf16 weights: qkv | proj | fc1 | fc2
#define W_QKV 0
#define W_PROJ (H3 * Cdim)
#define W_FC1  (W_PROJ + Cdim * Cdim)
#define W_FC2  (W_FC1 + HID * Cdim)
#define W_TOT  (W_FC2 + Cdim * HID)
__device__ bf16  g_wbf [(size_t)W_TOT];

// single launch: convert all 4 weight matrices to bf16
__global__ void cvt_all_kernel(const float* __restrict__ qkv_w,
                               const float* __restrict__ proj_w,
                               const float* __restrict__ fc1_w,
                               const float* __restrict__ fc2_w,
                               bf16* __restrict__ out)
{
    int i = blockIdx.x * blockDim.x + threadIdx.x;
    if (i >= W_TOT) return;
    float v;
    if (i < W_PROJ)      v = qkv_w[i];
    else if (i < W_FC1)  v = proj_w[i - W_PROJ];
    else if (i < W_FC2)  v = fc1_w[i - W_FC1];
    else                 v = fc2_w[i - W_FC2];
    out[i] = __float2bfloat16(v);
}

// ---------------------------------------------------------------------------
// Tiled fused cpe + LN (R8).
// ---------------------------------------------------------------------------
#define TJ 7
__global__ __launch_bounds__(Cdim)
void cpe_ln_kernel(const float* __restrict__ x,
                   const float* __restrict__ w,
                   const float* __restrict__ bias,
                   const float* __restrict__ lng,
                   const float* __restrict__ lnb,
                   float* __restrict__ y,
                   bf16* __restrict__ yln)
{
    __shared__ float tile[3][TJ + 2][Cdim];
    __shared__ float redS[12][TJ], redQ[12][TJ];
    __shared__ float stats[TJ][2];

    int c  = threadIdx.x;
    int jg = blockIdx.x;
    int i  = blockIdx.y;
    int b  = blockIdx.z;
    int j0 = jg * TJ;

    const float* xb = x + (size_t)b * Ntok * Cdim;

#pragma unroll
    for (int s = 0; s < 3 * (TJ + 2); s++) {
        int ri = s / (TJ + 2) + i - 1;
        int cj = s % (TJ + 2) + j0 - 1;
        float v = 0.f;
        if (ri >= 0 && ri < 28 && cj >= 0 && cj < 28)
            v = xb[(size_t)(ri * 28 + cj) * Cdim + c];
        tile[s / (TJ + 2)][s % (TJ + 2)][c] = v;
    }
    __syncthreads();

    const float* wc = w + c * 9;
    float wr[9];
#pragma unroll
    for (int q = 0; q < 9; q++) wr[q] = wc[q];
    float bs = bias[c];

    float val[TJ];
#pragma unroll
    for (int jt = 0; jt < TJ; jt++) {
        float acc = bs;
#pragma unroll
        for (int di = 0; di < 3; di++)
#pragma unroll
            for (int dj = 0; dj < 3; dj++)
                acc += wr[di * 3 + dj] * tile[di][jt + dj][c];
        val[jt] = tile[1][1 + jt][c] + acc;
    }

    int warp = c >> 5, lane = c & 31;
#pragma unroll
    for (int jt = 0; jt < TJ; jt++) {
        float s = val[jt], q = val[jt] * val[jt];
#pragma unroll
        for (int o = 16; o; o >>= 1) {
            s += __shfl_xor_sync(0xffffffffu, s, o);
            q += __shfl_xor_sync(0xffffffffu, q, o);
        }
        if (lane == 0) { redS[warp][jt] = s; redQ[warp][jt] = q; }
    }
    __syncthreads();
    if (c < TJ) {
        float ts = 0.f, tq = 0.f;
#pragma unroll
        for (int k = 0; k < 12; k++) { ts += redS[k][c]; tq += redQ[k][c]; }
        float mean = ts * (1.f / Cdim);
        float var  = tq * (1.f / Cdim) - mean * mean;
        stats[c][0] = mean;
        stats[c][1] = rsqrtf(var + 1e-5f);
    }
    __syncthreads();

    float gg = lng[c], bb = lnb[c];
#pragma unroll
    for (int jt = 0; jt < TJ; jt++) {
        size_t idx = ((size_t)b * Ntok + i * 28 + j0 + jt) * Cdim + c;
        float v = val[jt];
        y[idx] = v;
        yln[idx] = __float2bfloat16((v - stats[jt][0]) * stats[jt][1] * gg + bb);
    }
}

// ---------------------------------------------------------------------------
// bf16 GEMM (R8 config: best measured).
// ---------------------------------------------------------------------------
#define BM 128
#define BN 128
#define BK 32
#define STAGES 3
#define ASTG (BM * 64)
#define STG_BYTES (2 * ASTG)

__device__ __forceinline__ void cp16(unsigned saddr, const void* g)
{
    asm volatile("cp.async.cg.shared.global [%0], [%1], 16;\n" :: "r"(saddr), "l"(g));
}
__device__ __forceinline__ void ldsm4(uint32_t& r0, uint32_t& r1, uint32_t& r2,
                                      uint32_t& r3, uint32_t a)
{
    asm volatile("ldmatrix.sync.aligned.m8n8.x4.shared.b16 {%0,%1,%2,%3}, [%4];"
                 : "=r"(r0), "=r"(r1), "=r"(r2), "=r"(r3) : "r"(a));
}

template<int EPI, int K>
__global__ __launch_bounds__(256, 2)
void gemm_bf16(const bf16* __restrict__ A, const bf16* __restrict__ W,
               const float* __restrict__ bias, const float* __restrict__ res,
               void* __restrict__ Cout, int M, int N)
{
    __shared__ alignas(128) char sm[STAGES * STG_BYTES];
    uint32_t sb = (uint32_t)__cvta_generic_to_shared(sm);

    int tid = threadIdx.x;
    int w = tid >> 5, l = tid & 31;
    int row0 = blockIdx.y * BM;
    int col0 = blockIdx.x * BN;
    int wm = (w & 1) * 64;
    int wn = (w >> 1) * 32;
    int g = l >> 2, t = l & 3;

    int jj  = l >> 3;
    int rlo = l & 7;
    int rowA_in = (jj & 1) * 8 + rlo;
    int cA = jj >> 1;
    uint32_t aoff[4], axr[4];
#pragma unroll
    for (int mi = 0; mi < 4; mi++) {
        int rA = wm + mi * 16 + rowA_in;
        aoff[mi] = (uint32_t)rA * 64;
        axr[mi]  = (uint32_t)(((rA >> 1) & 3) << 4);
    }
    int rowB_in = (jj >> 1) * 8 + rlo;
    int cB = jj & 1;
    uint32_t boff[2], bxr[2];
#pragma unroll
    for (int p = 0; p < 2; p++) {
        int rB = wn + p * 16 + rowB_in;
        boff[p] = (uint32_t)(ASTG + rB * 64);
        bxr[p]  = (uint32_t)(((rB >> 1) & 3) << 4);
    }

    float acc[4][4][4];
#pragma unroll
    for (int mi = 0; mi < 4; mi++)
#pragma unroll
        for (int ni = 0; ni < 4; ni++)
#pragma unroll
            for (int r = 0; r < 4; r++) acc[mi][ni][r] = 0.f;

    constexpr int NS = K / BK;

    auto load_stage = [&](int s) {
        uint32_t tb = sb + (s % STAGES) * STG_BYTES;
        int kt = s * BK;
        const bf16* Ab = A + (size_t)row0 * K + kt;
        const bf16* Wb = W + (size_t)col0 * K + kt;
#pragma unroll
        for (int i = 0; i < 2; i++) {
            int id = tid + i * 256;
            int r = id >> 2, c = id & 3;
            int cs = c ^ ((r >> 1) & 3);
            cp16(tb + r * 64 + cs * 16, Ab + (size_t)r * K + c * 8);
            cp16(tb + ASTG + r * 64 + cs * 16, Wb + (size_t)r * K + c * 8);
        }
    };

    load_stage(0);
    asm volatile("cp.async.commit_group;\n");
    load_stage(1);
    asm volatile("cp.async.commit_group;\n");

#pragma unroll
    for (int s = 0; s < NS; s++) {
        asm volatile("cp.async.wait_group 1;\n");
        __syncthreads();

        if (s + STAGES - 1 < NS) load_stage(s + STAGES - 1);
        asm volatile("cp.async.commit_group;\n");

        uint32_t stb = sb + (s % STAGES) * STG_BYTES;
#pragma unroll
        for (int kk = 0; kk < 2; kk++) {
            uint32_t c0 = kk * 2;
            uint32_t af[4][4], bq[2][4];
#pragma unroll
            for (int mi = 0; mi < 4; mi++)
                ldsm4(af[mi][0], af[mi][1], af[mi][2], af[mi][3],
                      stb + aoff[mi] + ((((c0 + cA) << 4)) ^ axr[mi]));
#pragma unroll
            for (int p = 0; p < 2; p++)
                ldsm4(bq[p][0], bq[p][1], bq[p][2], bq[p][3],
                      stb + boff[p] + ((((c0 + cB) << 4)) ^ bxr[p]));

#pragma unroll
            for (int mi = 0; mi < 4; mi++)
#pragma unroll
                for (int ni = 0; ni < 4; ni++) {
                    int p = ni >> 1, q = ni & 1;
                    asm volatile(
                        "mma.sync.aligned.m16n8k16.row.col.f32.bf16.bf16.f32 "
                        "{%0,%1,%2,%3}, {%4,%5,%6,%7}, {%8,%9}, {%0,%1,%2,%3};"
                        : "+f"(acc[mi][ni][0]), "+f"(acc[mi][ni][1]),
                          "+f"(acc[mi][ni][2]), "+f"(acc[mi][ni][3])
                        : "r"(af[mi][0]), "r"(af[mi][1]), "r"(af[mi][2]), "r"(af[mi][3]),
                          "r"(bq[p][2 * q]), "r"(bq[p][2 * q + 1]));
                }
        }
    }

#pragma unroll
    for (int mi = 0; mi < 4; mi++) {
#pragma unroll
        for (int ni = 0; ni < 4; ni++) {
            int col = col0 + wn + ni * 8 + 2 * t;
#pragma unroll
            for (int half = 0; half < 2; half++) {
                int row = row0 + wm + mi * 16 + g + half * 8;
                size_t idx = (size_t)row * N + col;
                float v0 = acc[mi][ni][2 * half];
                float v1 = acc[mi][ni][2 * half + 1];
                if (EPI == 0) {
                    *(float2*)&((float*)Cout)[idx] = make_float2(v0, v1);
                } else if (EPI == 2) {
                    float2 bv = *(const float2*)&bias[col];
                    v0 += bv.x; v1 += bv.y;
                    v0 = 0.5f * v0 * (1.f + erff(v0 * 0.7071067811865475f));
                    v1 = 0.5f * v1 * (1.f + erff(v1 * 0.7071067811865475f));
                    __nv_bfloat162 pk;
                    pk.x = __float2bfloat16(v0);
                    pk.y = __float2bfloat16(v1);
                    *(__nv_bfloat162*)&((bf16*)Cout)[idx] = pk;
                } else {
                    float2 bv = *(const float2*)&bias[col];
                    float2 rv = *(const float2*)&res[idx];
                    v0 += bv.x + rv.x; v1 += bv.y + rv.y;
                    *(float2*)&((float*)Cout)[idx] = make_float2(v0, v1);
                }
            }
        }
    }
}

// ---------------------------------------------------------------------------
// Channel attention stage A: per (bh, chunk) partial (k*s)^T v over 112 tokens.
// 144 threads = 12x12 grid of 4x4 tiles; float4 LDG with REGISTER PREFETCH
// double-buffering (tile t+1 loads issue before tile t compute).
// Same load mapping & per-output fmaf order as R11/R12 -> bit-identical.
// ---------------------------------------------------------------------------
#define ATHR 144
#define KVS  56    // padded row stride (floats), 16B aligned
__global__ __launch_bounds__(ATHR, 7)
void attnA_partial(const float* __restrict__ qkv, float* __restrict__ partial)
{
    __shared__ float ks[16][KVS];
    __shared__ float vs[16][KVS];

    int bh = blockIdx.x;
    int b = bh >> 3, h = bh & 7;
    int chunk = blockIdx.y;
    int nstart = chunk * 112;
    int tid = threadIdx.x;
    int tx = tid % 12, ty = tid / 12;     // 12 x 12 tile grid
    const float scale = 0.14433756729740643f;   // 48^-0.5

    const float* base = qkv + (size_t)b * Ntok * H3 + h * HD;

    // static per-thread chunk mapping: slots tid, tid+144, tid+288(<384)
    int nn_s[3], d4_s[3], buf_s[3];
#pragma unroll
    for (int it = 0; it < 3; it++) {
        int idx = tid + it * ATHR;
        int bb2 = idx / 192;
        int rem = idx - bb2 * 192;
        buf_s[it] = bb2;
        nn_s[it]  = rem / 12;
        d4_s[it]  = rem - (rem / 12) * 12;
    }
    bool has2 = (tid < 96);

    float4 pf[3];
    auto prefetch = [&](int n0) {
#pragma unroll
        for (int it = 0; it < 3; it++) {
            if (it == 2 && !has2) break;
            const float* r = base + (size_t)(n0 + nn_s[it]) * H3
                           + (buf_s[it] ? 2 * Cdim : Cdim) + d4_s[it] * 4;
            pf[it] = *(const float4*)r;
        }
    };
    auto store_pf = [&]() {
#pragma unroll
        for (int it = 0; it < 3; it++) {
            if (it == 2 && !has2) break;
            float4 v4 = pf[it];
            if (buf_s[it] == 0) {
                v4.x *= scale; v4.y *= scale; v4.z *= scale; v4.w *= scale;
                *(float4*)&ks[nn_s[it]][d4_s[it] * 4] = v4;
            } else {
                *(float4*)&vs[nn_s[it]][d4_s[it] * 4] = v4;
            }
        }
    };

    float acc[4][4];
#pragma unroll
    for (int i = 0; i < 4; i++)
#pragma unroll
        for (int j = 0; j < 4; j++) acc[i][j] = 0.f;

    prefetch(nstart);

#pragma unroll
    for (int t = 0; t < 7; t++) {
        store_pf();
        __syncthreads();
        if (t < 6) prefetch(nstart + (t + 1) * 16);   // overlaps compute below
#pragma unroll
        for (int nn = 0; nn < 16; nn++) {
            float4 rk = *(const float4*)&ks[nn][ty * 4];
            float4 rv = *(const float4*)&vs[nn][tx * 4];
            float k[4] = {rk.x, rk.y, rk.z, rk.w};
            float v[4] = {rv.x, rv.y, rv.z, rv.w};
#pragma unroll
            for (int i = 0; i < 4; i++)
#pragma unroll
                for (int j = 0; j < 4; j++)
                    acc[i][j] = fmaf(k[i], v[j], acc[i][j]);
        }
        __syncthreads();
    }

    float* o = partial + ((size_t)chunk * (Bsz * NH) + bh) * (HD * HD);
#pragma unroll
    for (int i = 0; i < 4; i++) {
        float4 st = make_float4(acc[i][0], acc[i][1], acc[i][2], acc[i][3]);
        *(float4*)&o[(ty * 4 + i) * HD + tx * 4] = st;
    }
}

// ---------------------------------------------------------------------------
// Fused softmax + attnB, 2-way N split. Grid (256 bh, 2 halves), 384 threads.
// Both halves redundantly compute partial-sum + softmax (cheap, deterministic),
// then each processes 7 of the 14 token tiles. Per-output math identical.
// ---------------------------------------------------------------------------
__global__ __launch_bounds__(384)
void attnBF_kernel(const float* __restrict__ qkv, const float* __restrict__ partial,
                   bf16* __restrict__ out)
{
    __shared__ float at[HD * HD];
    __shared__ float qs[56][HD];

    int bh = blockIdx.x;
    int half = blockIdx.y;               // 0 or 1
    int b = bh >> 3, h = bh & 7;
    int tid = threadIdx.x;

#pragma unroll
    for (int it = 0; it < 6; it++) {
        int idx = tid + it * 384;
        float s = 0.f;
#pragma unroll
        for (int ch = 0; ch < NCHUNK; ch++)
            s += partial[((size_t)ch * (Bsz * NH) + bh) * (HD * HD) + idx];
        at[idx] = s;
    }
    __syncthreads();

    if (tid < HD) {
        float* row = &at[tid * HD];
        float m = -1e30f;
#pragma unroll
        for (int e = 0; e < HD; e++) m = fmaxf(m, row[e]);
        float s = 0.f;
#pragma unroll
        for (int e = 0; e < HD; e++) { float tv = expf(row[e] - m); row[e] = tv; s += tv; }
        float inv = 1.f / s;
#pragma unroll
        for (int e = 0; e < HD; e++) row[e] *= inv;
    }
    __syncthreads();

    int nl = tid / HD;
    int d  = tid - nl * HD;
    float4 arow[12];
#pragma unroll
    for (int e4 = 0; e4 < 12; e4++)
        arow[e4] = *(float4*)&at[d * HD + e4 * 4];

    const float* qb = qkv + (size_t)b * Ntok * H3 + h * HD + d;
    bf16* ob = out + (size_t)b * Ntok * Cdim + h * HD + d;

    int nbeg = half * 392;               // 7 tiles of 56 each
    for (int n0 = nbeg; n0 < nbeg + 392; n0 += 56) {
#pragma unroll
        for (int r = 0; r < 7; r++)
            qs[nl + 8 * r][d] = qb[(size_t)(n0 + nl + 8 * r) * H3];
        __syncthreads();

        float acc[7] = {0.f, 0.f, 0.f, 0.f, 0.f, 0.f, 0.f};
#pragma unroll
        for (int e4 = 0; e4 < 12; e4++) {
            float4 ar = arow[e4];
#pragma unroll
            for (int r = 0; r < 7; r++) {
                float4 qv = *(float4*)&qs[nl + 8 * r][e4 * 4];
                acc[r] = fmaf(ar.x, qv.x, acc[r]);
                acc[r] = fmaf(ar.y, qv.y, acc[r]);
                acc[r] = fmaf(ar.z, qv.z, acc[r]);
                acc[r] = fmaf(ar.w, qv.w, acc[r]);
            }
        }
#pragma unroll
        for (int r = 0; r < 7; r++)
            ob[(size_t)(n0 + nl + 8 * r) * Cdim] = __float2bfloat16(acc[r]);
        __syncthreads();
    }
}

// ---------------------------------------------------------------------------
// Launch
// ---------------------------------------------------------------------------
extern "C" void kernel_launch(void* const* d_in, const int* in_sizes, int n_in,
                              void* d_out, int out_size)
{
    const float* x       = (const float*)d_in[0];
    const float* cpe0_w  = (const float*)d_in[3];
    const float* cpe0_b  = (const float*)d_in[4];
    const float* cpe1_w  = (const float*)d_in[5];
    const float* cpe1_b  = (const float*)d_in[6];
    const float* norm1_g = (const float*)d_in[7];
    const float* norm1_b = (const float*)d_in[8];
    const float* qkv_w   = (const float*)d_in[9];
    const float* proj_w  = (const float*)d_in[10];
    const float* proj_b  = (const float*)d_in[11];
    const float* norm2_g = (const float*)d_in[12];
    const float* norm2_b = (const float*)d_in[13];
    const float* fc1_w   = (const float*)d_in[14];
    const float* fc1_b   = (const float*)d_in[15];
    const float* fc2_w   = (const float*)d_in[16];
    const float* fc2_b   = (const float*)d_in[17];
    float* out = (float*)d_out;

    float *xa, *qkvb, *attn, *xb;
    bf16 *ln, *att, *hbuf, *wbf;
    cudaGetSymbolAddress((void**)&xa,    g_xa);
    cudaGetSymbolAddress((void**)&ln,    g_ln);
    cudaGetSymbolAddress((void**)&qkvb,  g_qkv);
    cudaGetSymbolAddress((void**)&attn,  g_attn);
    cudaGetSymbolAddress((void**)&att,   g_att);
    cudaGetSymbolAddress((void**)&xb,    g_xb);
    cudaGetSymbolAddress((void**)&hbuf,  g_h);
    cudaGetSymbolAddress((void**)&wbf,   g_wbf);

    dim3 cpeGrid(4, 28, Bsz);

    // one launch: convert all weights to bf16
    cvt_all_kernel<<<(W_TOT + 255) / 256, 256>>>(qkv_w, proj_w, fc1_w, fc2_w, wbf);

    // xa = cpe0(x); ln = LN1(xa) [bf16]
    cpe_ln_kernel<<<cpeGrid, Cdim>>>(x, cpe0_w, cpe0_b, norm1_g, norm1_b, xa, ln);
    // qkv = ln1 @ qkv_w^T  (fp32 out)
    gemm_bf16<0, Cdim><<<dim3(H3 / BN, NT / BM), 256>>>(ln, wbf + W_QKV, nullptr, nullptr, qkvb, NT, H3);
    // channel attention
    attnA_partial<<<dim3(Bsz * NH, NCHUNK), ATHR>>>(qkvb, attn);
    attnBF_kernel<<<dim3(Bsz * NH, 2), 384>>>(qkvb, attn, att);
    // xb = xa + att @ proj_w^T + proj_b  (fp32 out)
    gemm_bf16<3, Cdim><<<dim3(Cdim / BN, NT / BM), 256>>>(att, wbf + W_PROJ, proj_b, xa, xb, NT, Cdim);
    // xc = cpe1(xb) -> xa ; ln = LN2(xc) [bf16]
    cpe_ln_kernel<<<cpeGrid, Cdim>>>(xb, cpe1_w, cpe1_b, norm2_g, norm2_b, xa, ln);
    // h = gelu(ln2 @ fc1^T + b1) [bf16 out]
    gemm_bf16<2, Cdim><<<dim3(HID / BN, NT / BM), 256>>>(ln, wbf + W_FC1, fc1_b, nullptr, hbuf, NT, HID);
    // out = xc + h @ fc2^T + b2 (fp32 out)
    gemm_bf16<3, HID><<<dim3(Cdim / BN, NT / BM), 256>>>(hbuf, wbf + W_FC2, fc2_b, xa, out, NT, Cdim);
}

// round 14
// speedup vs baseline: 1.0485x; 1.0438x over previous
#include <cuda_runtime.h>
#include <cuda_bf16.h>
#include <math.h>
#include <stdint.h>

// ---------------------------------------------------------------------------
// ChannelBlock: B=32, N=784 (28x28), C=384, heads=8, hd=48, MLP hidden=1536
// bf16 mma.sync GEMMs (R8 config), 4x7-tiled cpe_ln (dynamic smem),
// double-buffered prefetch attnA, fused softmax+attnB (2-way split).
// ---------------------------------------------------------------------------

#define Bsz   32
#define Ntok  784
#define Cdim  384
#define NT    (Bsz * Ntok)     // 25088
#define H3    (3 * Cdim)       // 1152
#define HID   1536
#define NH    8
#define HD    48
#define NCHUNK 7               // attnA token chunks (112 each)

typedef __nv_bfloat16 bf16;

// scratch (static device memory; no allocation anywhere)
__device__ float g_xa  [(size_t)NT * Cdim];
__device__ bf16  g_ln  [(size_t)NT * Cdim];
__device__ float g_qkv [(size_t)NT * H3];
__device__ float g_attn[(size_t)NCHUNK * Bsz * NH * HD * HD];  // partial logits
__device__ bf16  g_att [(size_t)NT * Cdim];
__device__ float g_xb  [(size_t)NT * Cdim];
__device__ bf16  g_h   [(size_t)NT * HID];
// bf16 weights: qkv | proj | fc1 | fc2
#define W_QKV 0
#define W_PROJ (H3 * Cdim)
#define W_FC1  (W_PROJ + Cdim * Cdim)
#define W_FC2  (W_FC1 + HID * Cdim)
#define W_TOT  (W_FC2 + Cdim * HID)
__device__ bf16  g_wbf [(size_t)W_TOT];

// single launch: convert all 4 weight matrices to bf16
__global__ void cvt_all_kernel(const float* __restrict__ qkv_w,
                               const float* __restrict__ proj_w,
                               const float* __restrict__ fc1_w,
                               const float* __restrict__ fc2_w,
                               bf16* __restrict__ out)
{
    int i = blockIdx.x * blockDim.x + threadIdx.x;
    if (i >= W_TOT) return;
    float v;
    if (i < W_PROJ)      v = qkv_w[i];
    else if (i < W_FC1)  v = proj_w[i - W_PROJ];
    else if (i < W_FC2)  v = fc1_w[i - W_FC1];
    else                 v = fc2_w[i - W_FC2];
    out[i] = __float2bfloat16(v);
}

// ---------------------------------------------------------------------------
// Tiled fused cpe + LN: 4 rows x 7 cols of tokens per block (28 tokens),
// 6x9 halo tile in dynamic smem. Same per-token op order as before.
// ---------------------------------------------------------------------------
#define TJC 7
#define TIR 4
#define NTOK_B (TIR * TJC)                 // 28 tokens per block
#define SLOTS ((TIR + 2) * (TJC + 2))      // 54 halo slots
#define CPE_SMEM ((SLOTS * Cdim + 2 * 12 * NTOK_B + 2 * NTOK_B) * 4)

__global__ __launch_bounds__(Cdim)
void cpe_ln_kernel(const float* __restrict__ x,
                   const float* __restrict__ w,
                   const float* __restrict__ bias,
                   const float* __restrict__ lng,
                   const float* __restrict__ lnb,
                   float* __restrict__ y,
                   bf16* __restrict__ yln)
{
    extern __shared__ float dsm[];
    float (*tile)[TJC + 2][Cdim] = (float (*)[TJC + 2][Cdim])dsm;
    float* redS  = dsm + SLOTS * Cdim;
    float* redQ  = redS + 12 * NTOK_B;
    float* stats = redQ + 12 * NTOK_B;     // [NTOK_B][2]

    int c  = threadIdx.x;
    int jg = blockIdx.x;                   // 0..3
    int ig = blockIdx.y;                   // 0..6
    int b  = blockIdx.z;
    int j0 = jg * TJC, i0 = ig * TIR;

    const float* xb = x + (size_t)b * Ntok * Cdim;

#pragma unroll
    for (int s = 0; s < SLOTS; s++) {
        int ri = s / (TJC + 2) + i0 - 1;
        int cj = s % (TJC + 2) + j0 - 1;
        float v = 0.f;
        if (ri >= 0 && ri < 28 && cj >= 0 && cj < 28)
            v = xb[(size_t)(ri * 28 + cj) * Cdim + c];
        tile[s / (TJC + 2)][s % (TJC + 2)][c] = v;
    }
    __syncthreads();

    const float* wc = w + c * 9;
    float wr[9];
#pragma unroll
    for (int q = 0; q < 9; q++) wr[q] = wc[q];
    float bs = bias[c];

    float val[NTOK_B];
#pragma unroll
    for (int r = 0; r < TIR; r++) {
#pragma unroll
        for (int jt = 0; jt < TJC; jt++) {
            float acc = bs;
#pragma unroll
            for (int di = 0; di < 3; di++)
#pragma unroll
                for (int dj = 0; dj < 3; dj++)
                    acc += wr[di * 3 + dj] * tile[r + di][jt + dj][c];
            val[r * TJC + jt] = tile[r + 1][jt + 1][c] + acc;
        }
    }

    int warp = c >> 5, lane = c & 31;
#pragma unroll
    for (int q = 0; q < NTOK_B; q++) {
        float s = val[q], sq = val[q] * val[q];
#pragma unroll
        for (int o = 16; o; o >>= 1) {
            s  += __shfl_xor_sync(0xffffffffu, s,  o);
            sq += __shfl_xor_sync(0xffffffffu, sq, o);
        }
        if (lane == 0) { redS[warp * NTOK_B + q] = s; redQ[warp * NTOK_B + q] = sq; }
    }
    __syncthreads();
    if (c < NTOK_B) {
        float ts = 0.f, tq = 0.f;
#pragma unroll
        for (int k = 0; k < 12; k++) { ts += redS[k * NTOK_B + c]; tq += redQ[k * NTOK_B + c]; }
        float mean = ts * (1.f / Cdim);
        float var  = tq * (1.f / Cdim) - mean * mean;
        stats[c * 2]     = mean;
        stats[c * 2 + 1] = rsqrtf(var + 1e-5f);
    }
    __syncthreads();

    float gg = lng[c], bb = lnb[c];
#pragma unroll
    for (int r = 0; r < TIR; r++) {
#pragma unroll
        for (int jt = 0; jt < TJC; jt++) {
            int q = r * TJC + jt;
            size_t idx = ((size_t)b * Ntok + (i0 + r) * 28 + j0 + jt) * Cdim + c;
            float v = val[q];
            y[idx] = v;
            yln[idx] = __float2bfloat16((v - stats[q * 2]) * stats[q * 2 + 1] * gg + bb);
        }
    }
}

// ---------------------------------------------------------------------------
// bf16 GEMM (R8 config: best measured).
// ---------------------------------------------------------------------------
#define BM 128
#define BN 128
#define BK 32
#define STAGES 3
#define ASTG (BM * 64)
#define STG_BYTES (2 * ASTG)

__device__ __forceinline__ void cp16(unsigned saddr, const void* g)
{
    asm volatile("cp.async.cg.shared.global [%0], [%1], 16;\n" :: "r"(saddr), "l"(g));
}
__device__ __forceinline__ void ldsm4(uint32_t& r0, uint32_t& r1, uint32_t& r2,
                                      uint32_t& r3, uint32_t a)
{
    asm volatile("ldmatrix.sync.aligned.m8n8.x4.shared.b16 {%0,%1,%2,%3}, [%4];"
                 : "=r"(r0), "=r"(r1), "=r"(r2), "=r"(r3) : "r"(a));
}

template<int EPI, int K>
__global__ __launch_bounds__(256, 2)
void gemm_bf16(const bf16* __restrict__ A, const bf16* __restrict__ W,
               const float* __restrict__ bias, const float* __restrict__ res,
               void* __restrict__ Cout, int M, int N)
{
    __shared__ alignas(128) char sm[STAGES * STG_BYTES];
    uint32_t sb = (uint32_t)__cvta_generic_to_shared(sm);

    int tid = threadIdx.x;
    int w = tid >> 5, l = tid & 31;
    int row0 = blockIdx.y * BM;
    int col0 = blockIdx.x * BN;
    int wm = (w & 1) * 64;
    int wn = (w >> 1) * 32;
    int g = l >> 2, t = l & 3;

    int jj  = l >> 3;
    int rlo = l & 7;
    int rowA_in = (jj & 1) * 8 + rlo;
    int cA = jj >> 1;
    uint32_t aoff[4], axr[4];
#pragma unroll
    for (int mi = 0; mi < 4; mi++) {
        int rA = wm + mi * 16 + rowA_in;
        aoff[mi] = (uint32_t)rA * 64;
        axr[mi]  = (uint32_t)(((rA >> 1) & 3) << 4);
    }
    int rowB_in = (jj >> 1) * 8 + rlo;
    int cB = jj & 1;
    uint32_t boff[2], bxr[2];
#pragma unroll
    for (int p = 0; p < 2; p++) {
        int rB = wn + p * 16 + rowB_in;
        boff[p] = (uint32_t)(ASTG + rB * 64);
        bxr[p]  = (uint32_t)(((rB >> 1) & 3) << 4);
    }

    float acc[4][4][4];
#pragma unroll
    for (int mi = 0; mi < 4; mi++)
#pragma unroll
        for (int ni = 0; ni < 4; ni++)
#pragma unroll
            for (int r = 0; r < 4; r++) acc[mi][ni][r] = 0.f;

    constexpr int NS = K / BK;

    auto load_stage = [&](int s) {
        uint32_t tb = sb + (s % STAGES) * STG_BYTES;
        int kt = s * BK;
        const bf16* Ab = A + (size_t)row0 * K + kt;
        const bf16* Wb = W + (size_t)col0 * K + kt;
#pragma unroll
        for (int i = 0; i < 2; i++) {
            int id = tid + i * 256;
            int r = id >> 2, c = id & 3;
            int cs = c ^ ((r >> 1) & 3);
            cp16(tb + r * 64 + cs * 16, Ab + (size_t)r * K + c * 8);
            cp16(tb + ASTG + r * 64 + cs * 16, Wb + (size_t)r * K + c * 8);
        }
    };

    load_stage(0);
    asm volatile("cp.async.commit_group;\n");
    load_stage(1);
    asm volatile("cp.async.commit_group;\n");

#pragma unroll
    for (int s = 0; s < NS; s++) {
        asm volatile("cp.async.wait_group 1;\n");
        __syncthreads();

        if (s + STAGES - 1 < NS) load_stage(s + STAGES - 1);
        asm volatile("cp.async.commit_group;\n");

        uint32_t stb = sb + (s % STAGES) * STG_BYTES;
#pragma unroll
        for (int kk = 0; kk < 2; kk++) {
            uint32_t c0 = kk * 2;
            uint32_t af[4][4], bq[2][4];
#pragma unroll
            for (int mi = 0; mi < 4; mi++)
                ldsm4(af[mi][0], af[mi][1], af[mi][2], af[mi][3],
                      stb + aoff[mi] + ((((c0 + cA) << 4)) ^ axr[mi]));
#pragma unroll
            for (int p = 0; p < 2; p++)
                ldsm4(bq[p][0], bq[p][1], bq[p][2], bq[p][3],
                      stb + boff[p] + ((((c0 + cB) << 4)) ^ bxr[p]));

#pragma unroll
            for (int mi = 0; mi < 4; mi++)
#pragma unroll
                for (int ni = 0; ni < 4; ni++) {
                    int p = ni >> 1, q = ni & 1;
                    asm volatile(
                        "mma.sync.aligned.m16n8k16.row.col.f32.bf16.bf16.f32 "
                        "{%0,%1,%2,%3}, {%4,%5,%6,%7}, {%8,%9}, {%0,%1,%2,%3};"
                        : "+f"(acc[mi][ni][0]), "+f"(acc[mi][ni][1]),
                          "+f"(acc[mi][ni][2]), "+f"(acc[mi][ni][3])
                        : "r"(af[mi][0]), "r"(af[mi][1]), "r"(af[mi][2]), "r"(af[mi][3]),
                          "r"(bq[p][2 * q]), "r"(bq[p][2 * q + 1]));
                }
        }
    }

#pragma unroll
    for (int mi = 0; mi < 4; mi++) {
#pragma unroll
        for (int ni = 0; ni < 4; ni++) {
            int col = col0 + wn + ni * 8 + 2 * t;
#pragma unroll
            for (int half = 0; half < 2; half++) {
                int row = row0 + wm + mi * 16 + g + half * 8;
                size_t idx = (size_t)row * N + col;
                float v0 = acc[mi][ni][2 * half];
                float v1 = acc[mi][ni][2 * half + 1];
                if (EPI == 0) {
                    *(float2*)&((float*)Cout)[idx] = make_float2(v0, v1);
                } else if (EPI == 2) {
                    float2 bv = *(const float2*)&bias[col];
                    v0 += bv.x; v1 += bv.y;
                    v0 = 0.5f * v0 * (1.f + erff(v0 * 0.7071067811865475f));
                    v1 = 0.5f * v1 * (1.f + erff(v1 * 0.7071067811865475f));
                    __nv_bfloat162 pk;
                    pk.x = __float2bfloat16(v0);
                    pk.y = __float2bfloat16(v1);
                    *(__nv_bfloat162*)&((bf16*)Cout)[idx] = pk;
                } else {
                    float2 bv = *(const float2*)&bias[col];
                    float2 rv = *(const float2*)&res[idx];
                    v0 += bv.x + rv.x; v1 += bv.y + rv.y;
                    *(float2*)&((float*)Cout)[idx] = make_float2(v0, v1);
                }
            }
        }
    }
}

// ---------------------------------------------------------------------------
// Channel attention stage A: per (bh, chunk) partial (k*s)^T v over 112 tokens.
// 144 threads, 4x4 tiles, float4 LDG register prefetch + DOUBLE-BUFFERED smem:
// one __syncthreads per tile; stores for tile t+1 issue after compute of t.
// Same loads and per-output fmaf order -> bit-identical.
// ---------------------------------------------------------------------------
#define ATHR 144
#define KVS  56    // padded row stride (floats), 16B aligned
__global__ __launch_bounds__(ATHR, 7)
void attnA_partial(const float* __restrict__ qkv, float* __restrict__ partial)
{
    __shared__ float ks[2][16][KVS];
    __shared__ float vs[2][16][KVS];

    int bh = blockIdx.x;
    int b = bh >> 3, h = bh & 7;
    int chunk = blockIdx.y;
    int nstart = chunk * 112;
    int tid = threadIdx.x;
    int tx = tid % 12, ty = tid / 12;
    const float scale = 0.14433756729740643f;   // 48^-0.5

    const float* base = qkv + (size_t)b * Ntok * H3 + h * HD;

    // static per-thread chunk mapping: slots tid, tid+144, tid+288(<384)
    int nn_s[3], d4_s[3], buf_s[3];
#pragma unroll
    for (int it = 0; it < 3; it++) {
        int idx = tid + it * ATHR;
        int bb2 = idx / 192;
        int rem = idx - bb2 * 192;
        buf_s[it] = bb2;
        nn_s[it]  = rem / 12;
        d4_s[it]  = rem - (rem / 12) * 12;
    }
    bool has2 = (tid < 96);

    float4 pf[3];
    auto prefetch = [&](int n0) {
#pragma unroll
        for (int it = 0; it < 3; it++) {
            if (it == 2 && !has2) break;
            const float* r = base + (size_t)(n0 + nn_s[it]) * H3
                           + (buf_s[it] ? 2 * Cdim : Cdim) + d4_s[it] * 4;
            pf[it] = *(const float4*)r;
        }
    };
    auto store_pf = [&](int sb2) {
#pragma unroll
        for (int it = 0; it < 3; it++) {
            if (it == 2 && !has2) break;
            float4 v4 = pf[it];
            if (buf_s[it] == 0) {
                v4.x *= scale; v4.y *= scale; v4.z *= scale; v4.w *= scale;
                *(float4*)&ks[sb2][nn_s[it]][d4_s[it] * 4] = v4;
            } else {
                *(float4*)&vs[sb2][nn_s[it]][d4_s[it] * 4] = v4;
            }
        }
    };

    float acc[4][4];
#pragma unroll
    for (int i = 0; i < 4; i++)
#pragma unroll
        for (int j = 0; j < 4; j++) acc[i][j] = 0.f;

    prefetch(nstart);
    store_pf(0);
    __syncthreads();

#pragma unroll
    for (int t = 0; t < 7; t++) {
        if (t < 6) prefetch(nstart + (t + 1) * 16);
        int cb = t & 1;
#pragma unroll
        for (int nn = 0; nn < 16; nn++) {
            float4 rk = *(const float4*)&ks[cb][nn][ty * 4];
            float4 rv = *(const float4*)&vs[cb][nn][tx * 4];
            float k[4] = {rk.x, rk.y, rk.z, rk.w};
            float v[4] = {rv.x, rv.y, rv.z, rv.w};
#pragma unroll
            for (int i = 0; i < 4; i++)
#pragma unroll
                for (int j = 0; j < 4; j++)
                    acc[i][j] = fmaf(k[i], v[j], acc[i][j]);
        }
        if (t < 6) store_pf((t + 1) & 1);
        __syncthreads();
    }

    float* o = partial + ((size_t)chunk * (Bsz * NH) + bh) * (HD * HD);
#pragma unroll
    for (int i = 0; i < 4; i++) {
        float4 st = make_float4(acc[i][0], acc[i][1], acc[i][2], acc[i][3]);
        *(float4*)&o[(ty * 4 + i) * HD + tx * 4] = st;
    }
}

// ---------------------------------------------------------------------------
// Fused softmax + attnB, 2-way N split (R13).
// ---------------------------------------------------------------------------
__global__ __launch_bounds__(384)
void attnBF_kernel(const float* __restrict__ qkv, const float* __restrict__ partial,
                   bf16* __restrict__ out)
{
    __shared__ float at[HD * HD];
    __shared__ float qs[56][HD];

    int bh = blockIdx.x;
    int half = blockIdx.y;
    int b = bh >> 3, h = bh & 7;
    int tid = threadIdx.x;

#pragma unroll
    for (int it = 0; it < 6; it++) {
        int idx = tid + it * 384;
        float s = 0.f;
#pragma unroll
        for (int ch = 0; ch < NCHUNK; ch++)
            s += partial[((size_t)ch * (Bsz * NH) + bh) * (HD * HD) + idx];
        at[idx] = s;
    }
    __syncthreads();

    if (tid < HD) {
        float* row = &at[tid * HD];
        float m = -1e30f;
#pragma unroll
        for (int e = 0; e < HD; e++) m = fmaxf(m, row[e]);
        float s = 0.f;
#pragma unroll
        for (int e = 0; e < HD; e++) { float tv = expf(row[e] - m); row[e] = tv; s += tv; }
        float inv = 1.f / s;
#pragma unroll
        for (int e = 0; e < HD; e++) row[e] *= inv;
    }
    __syncthreads();

    int nl = tid / HD;
    int d  = tid - nl * HD;
    float4 arow[12];
#pragma unroll
    for (int e4 = 0; e4 < 12; e4++)
        arow[e4] = *(float4*)&at[d * HD + e4 * 4];

    const float* qb = qkv + (size_t)b * Ntok * H3 + h * HD + d;
    bf16* ob = out + (size_t)b * Ntok * Cdim + h * HD + d;

    int nbeg = half * 392;
    for (int n0 = nbeg; n0 < nbeg + 392; n0 += 56) {
#pragma unroll
        for (int r = 0; r < 7; r++)
            qs[nl + 8 * r][d] = qb[(size_t)(n0 + nl + 8 * r) * H3];
        __syncthreads();

        float acc[7] = {0.f, 0.f, 0.f, 0.f, 0.f, 0.f, 0.f};
#pragma unroll
        for (int e4 = 0; e4 < 12; e4++) {
            float4 ar = arow[e4];
#pragma unroll
            for (int r = 0; r < 7; r++) {
                float4 qv = *(float4*)&qs[nl + 8 * r][e4 * 4];
                acc[r] = fmaf(ar.x, qv.x, acc[r]);
                acc[r] = fmaf(ar.y, qv.y, acc[r]);
                acc[r] = fmaf(ar.z, qv.z, acc[r]);
                acc[r] = fmaf(ar.w, qv.w, acc[r]);
            }
        }
#pragma unroll
        for (int r = 0; r < 7; r++)
            ob[(size_t)(n0 + nl + 8 * r) * Cdim] = __float2bfloat16(acc[r]);
        __syncthreads();
    }
}

// ---------------------------------------------------------------------------
// Launch
// ---------------------------------------------------------------------------
extern "C" void kernel_launch(void* const* d_in, const int* in_sizes, int n_in,
                              void* d_out, int out_size)
{
    const float* x       = (const float*)d_in[0];
    const float* cpe0_w  = (const float*)d_in[3];
    const float* cpe0_b  = (const float*)d_in[4];
    const float* cpe1_w  = (const float*)d_in[5];
    const float* cpe1_b  = (const float*)d_in[6];
    const float* norm1_g = (const float*)d_in[7];
    const float* norm1_b = (const float*)d_in[8];
    const float* qkv_w   = (const float*)d_in[9];
    const float* proj_w  = (const float*)d_in[10];
    const float* proj_b  = (const float*)d_in[11];
    const float* norm2_g = (const float*)d_in[12];
    const float* norm2_b = (const float*)d_in[13];
    const float* fc1_w   = (const float*)d_in[14];
    const float* fc1_b   = (const float*)d_in[15];
    const float* fc2_w   = (const float*)d_in[16];
    const float* fc2_b   = (const float*)d_in[17];
    float* out = (float*)d_out;

    float *xa, *qkvb, *attn, *xb;
    bf16 *ln, *att, *hbuf, *wbf;
    cudaGetSymbolAddress((void**)&xa,    g_xa);
    cudaGetSymbolAddress((void**)&ln,    g_ln);
    cudaGetSymbolAddress((void**)&qkvb,  g_qkv);
    cudaGetSymbolAddress((void**)&attn,  g_attn);
    cudaGetSymbolAddress((void**)&att,   g_att);
    cudaGetSymbolAddress((void**)&xb,    g_xb);
    cudaGetSymbolAddress((void**)&hbuf,  g_h);
    cudaGetSymbolAddress((void**)&wbf,   g_wbf);

    // allow large dynamic smem for cpe_ln (host-side attr set; not a stream op)
    cudaFuncSetAttribute(cpe_ln_kernel, cudaFuncAttributeMaxDynamicSharedMemorySize, CPE_SMEM);

    dim3 cpeGrid(4, TJC, Bsz);   // 4 col-groups x 7 row-groups x batch

    // one launch: convert all weights to bf16
    cvt_all_kernel<<<(W_TOT + 255) / 256, 256>>>(qkv_w, proj_w, fc1_w, fc2_w, wbf);

    // xa = cpe0(x); ln = LN1(xa) [bf16]
    cpe_ln_kernel<<<cpeGrid, Cdim, CPE_SMEM>>>(x, cpe0_w, cpe0_b, norm1_g, norm1_b, xa, ln);
    // qkv = ln1 @ qkv_w^T  (fp32 out)
    gemm_bf16<0, Cdim><<<dim3(H3 / BN, NT / BM), 256>>>(ln, wbf + W_QKV, nullptr, nullptr, qkvb, NT, H3);
    // channel attention
    attnA_partial<<<dim3(Bsz * NH, NCHUNK), ATHR>>>(qkvb, attn);
    attnBF_kernel<<<dim3(Bsz * NH, 2), 384>>>(qkvb, attn, att);
    // xb = xa + att @ proj_w^T + proj_b  (fp32 out)
    gemm_bf16<3, Cdim><<<dim3(Cdim / BN, NT / BM), 256>>>(att, wbf + W_PROJ, proj_b, xa, xb, NT, Cdim);
    // xc = cpe1(xb) -> xa ; ln = LN2(xc) [bf16]
    cpe_ln_kernel<<<cpeGrid, Cdim, CPE_SMEM>>>(xb, cpe1_w, cpe1_b, norm2_g, norm2_b, xa, ln);
    // h = gelu(ln2 @ fc1^T + b1) [bf16 out]
    gemm_bf16<2, Cdim><<<dim3(HID / BN, NT / BM), 256>>>(ln, wbf + W_FC1, fc1_b, nullptr, hbuf, NT, HID);
    // out = xc + h @ fc2^T + b2 (fp32 out)
    gemm_bf16<3, HID><<<dim3(Cdim / BN, NT / BM), 256>>>(hbuf, wbf + W_FC2, fc2_b, xa, out, NT, Cdim);
}

// round 15
// speedup vs baseline: 1.0634x; 1.0142x over previous
#include <cuda_runtime.h>
#include <cuda_bf16.h>
#include <math.h>
#include <stdint.h>

// ---------------------------------------------------------------------------
// ChannelBlock: B=32, N=784 (28x28), C=384, heads=8, hd=48, MLP hidden=1536
// bf16 mma.sync GEMMs (R8 config - at legacy-HMMA pipe ceiling),
// 4x7-tiled cpe_ln, nn-pipelined attnA, fused softmax+attnB (float4 sums).
// ---------------------------------------------------------------------------

#define Bsz   32
#define Ntok  784
#define Cdim  384
#define NT    (Bsz * Ntok)     // 25088
#define H3    (3 * Cdim)       // 1152
#define HID   1536
#define NH    8
#define HD    48
#define NCHUNK 7               // attnA token chunks (112 each)

typedef __nv_bfloat16 bf16;

// scratch (static device memory; no allocation anywhere)
__device__ float g_xa  [(size_t)NT * Cdim];
__device__ bf16  g_ln  [(size_t)NT * Cdim];
__device__ float g_qkv [(size_t)NT * H3];
__device__ float g_attn[(size_t)NCHUNK * Bsz * NH * HD * HD];  // partial logits
__device__ bf16  g_att [(size_t)NT * Cdim];
__device__ float g_xb  [(size_t)NT * Cdim];
__device__ bf16  g_h   [(size_t)NT * HID];
// bf16 weights: qkv | proj | fc1 | fc2
#define W_QKV 0
#define W_PROJ (H3 * Cdim)
#define W_FC1  (W_PROJ + Cdim * Cdim)
#define W_FC2  (W_FC1 + HID * Cdim)
#define W_TOT  (W_FC2 + Cdim * HID)
__device__ bf16  g_wbf [(size_t)W_TOT];

// single launch: convert all 4 weight matrices to bf16
__global__ void cvt_all_kernel(const float* __restrict__ qkv_w,
                               const float* __restrict__ proj_w,
                               const float* __restrict__ fc1_w,
                               const float* __restrict__ fc2_w,
                               bf16* __restrict__ out)
{
    int i = blockIdx.x * blockDim.x + threadIdx.x;
    if (i >= W_TOT) return;
    float v;
    if (i < W_PROJ)      v = qkv_w[i];
    else if (i < W_FC1)  v = proj_w[i - W_PROJ];
    else if (i < W_FC2)  v = fc1_w[i - W_FC1];
    else                 v = fc2_w[i - W_FC2];
    out[i] = __float2bfloat16(v);
}

// ---------------------------------------------------------------------------
// Tiled fused cpe + LN: 4 rows x 7 cols of tokens per block (28 tokens),
// 6x9 halo tile in dynamic smem (R14).
// ---------------------------------------------------------------------------
#define TJC 7
#define TIR 4
#define NTOK_B (TIR * TJC)                 // 28 tokens per block
#define SLOTS ((TIR + 2) * (TJC + 2))      // 54 halo slots
#define CPE_SMEM ((SLOTS * Cdim + 2 * 12 * NTOK_B + 2 * NTOK_B) * 4)

__global__ __launch_bounds__(Cdim)
void cpe_ln_kernel(const float* __restrict__ x,
                   const float* __restrict__ w,
                   const float* __restrict__ bias,
                   const float* __restrict__ lng,
                   const float* __restrict__ lnb,
                   float* __restrict__ y,
                   bf16* __restrict__ yln)
{
    extern __shared__ float dsm[];
    float (*tile)[TJC + 2][Cdim] = (float (*)[TJC + 2][Cdim])dsm;
    float* redS  = dsm + SLOTS * Cdim;
    float* redQ  = redS + 12 * NTOK_B;
    float* stats = redQ + 12 * NTOK_B;     // [NTOK_B][2]

    int c  = threadIdx.x;
    int jg = blockIdx.x;                   // 0..3
    int ig = blockIdx.y;                   // 0..6
    int b  = blockIdx.z;
    int j0 = jg * TJC, i0 = ig * TIR;

    const float* xb = x + (size_t)b * Ntok * Cdim;

#pragma unroll
    for (int s = 0; s < SLOTS; s++) {
        int ri = s / (TJC + 2) + i0 - 1;
        int cj = s % (TJC + 2) + j0 - 1;
        float v = 0.f;
        if (ri >= 0 && ri < 28 && cj >= 0 && cj < 28)
            v = xb[(size_t)(ri * 28 + cj) * Cdim + c];
        tile[s / (TJC + 2)][s % (TJC + 2)][c] = v;
    }
    __syncthreads();

    const float* wc = w + c * 9;
    float wr[9];
#pragma unroll
    for (int q = 0; q < 9; q++) wr[q] = wc[q];
    float bs = bias[c];

    float val[NTOK_B];
#pragma unroll
    for (int r = 0; r < TIR; r++) {
#pragma unroll
        for (int jt = 0; jt < TJC; jt++) {
            float acc = bs;
#pragma unroll
            for (int di = 0; di < 3; di++)
#pragma unroll
                for (int dj = 0; dj < 3; dj++)
                    acc += wr[di * 3 + dj] * tile[r + di][jt + dj][c];
            val[r * TJC + jt] = tile[r + 1][jt + 1][c] + acc;
        }
    }

    int warp = c >> 5, lane = c & 31;
#pragma unroll
    for (int q = 0; q < NTOK_B; q++) {
        float s = val[q], sq = val[q] * val[q];
#pragma unroll
        for (int o = 16; o; o >>= 1) {
            s  += __shfl_xor_sync(0xffffffffu, s,  o);
            sq += __shfl_xor_sync(0xffffffffu, sq, o);
        }
        if (lane == 0) { redS[warp * NTOK_B + q] = s; redQ[warp * NTOK_B + q] = sq; }
    }
    __syncthreads();
    if (c < NTOK_B) {
        float ts = 0.f, tq = 0.f;
#pragma unroll
        for (int k = 0; k < 12; k++) { ts += redS[k * NTOK_B + c]; tq += redQ[k * NTOK_B + c]; }
        float mean = ts * (1.f / Cdim);
        float var  = tq * (1.f / Cdim) - mean * mean;
        stats[c * 2]     = mean;
        stats[c * 2 + 1] = rsqrtf(var + 1e-5f);
    }
    __syncthreads();

    float gg = lng[c], bb = lnb[c];
#pragma unroll
    for (int r = 0; r < TIR; r++) {
#pragma unroll
        for (int jt = 0; jt < TJC; jt++) {
            int q = r * TJC + jt;
            size_t idx = ((size_t)b * Ntok + (i0 + r) * 28 + j0 + jt) * Cdim + c;
            float v = val[q];
            y[idx] = v;
            yln[idx] = __float2bfloat16((v - stats[q * 2]) * stats[q * 2 + 1] * gg + bb);
        }
    }
}

// ---------------------------------------------------------------------------
// bf16 GEMM (R8 config: at legacy HMMA pipe ceiling — do not touch).
// ---------------------------------------------------------------------------
#define BM 128
#define BN 128
#define BK 32
#define STAGES 3
#define ASTG (BM * 64)
#define STG_BYTES (2 * ASTG)

__device__ __forceinline__ void cp16(unsigned saddr, const void* g)
{
    asm volatile("cp.async.cg.shared.global [%0], [%1], 16;\n" :: "r"(saddr), "l"(g));
}
__device__ __forceinline__ void ldsm4(uint32_t& r0, uint32_t& r1, uint32_t& r2,
                                      uint32_t& r3, uint32_t a)
{
    asm volatile("ldmatrix.sync.aligned.m8n8.x4.shared.b16 {%0,%1,%2,%3}, [%4];"
                 : "=r"(r0), "=r"(r1), "=r"(r2), "=r"(r3) : "r"(a));
}

template<int EPI, int K>
__global__ __launch_bounds__(256, 2)
void gemm_bf16(const bf16* __restrict__ A, const bf16* __restrict__ W,
               const float* __restrict__ bias, const float* __restrict__ res,
               void* __restrict__ Cout, int M, int N)
{
    __shared__ alignas(128) char sm[STAGES * STG_BYTES];
    uint32_t sb = (uint32_t)__cvta_generic_to_shared(sm);

    int tid = threadIdx.x;
    int w = tid >> 5, l = tid & 31;
    int row0 = blockIdx.y * BM;
    int col0 = blockIdx.x * BN;
    int wm = (w & 1) * 64;
    int wn = (w >> 1) * 32;
    int g = l >> 2, t = l & 3;

    int jj  = l >> 3;
    int rlo = l & 7;
    int rowA_in = (jj & 1) * 8 + rlo;
    int cA = jj >> 1;
    uint32_t aoff[4], axr[4];
#pragma unroll
    for (int mi = 0; mi < 4; mi++) {
        int rA = wm + mi * 16 + rowA_in;
        aoff[mi] = (uint32_t)rA * 64;
        axr[mi]  = (uint32_t)(((rA >> 1) & 3) << 4);
    }
    int rowB_in = (jj >> 1) * 8 + rlo;
    int cB = jj & 1;
    uint32_t boff[2], bxr[2];
#pragma unroll
    for (int p = 0; p < 2; p++) {
        int rB = wn + p * 16 + rowB_in;
        boff[p] = (uint32_t)(ASTG + rB * 64);
        bxr[p]  = (uint32_t)(((rB >> 1) & 3) << 4);
    }

    float acc[4][4][4];
#pragma unroll
    for (int mi = 0; mi < 4; mi++)
#pragma unroll
        for (int ni = 0; ni < 4; ni++)
#pragma unroll
            for (int r = 0; r < 4; r++) acc[mi][ni][r] = 0.f;

    constexpr int NS = K / BK;

    auto load_stage = [&](int s) {
        uint32_t tb = sb + (s % STAGES) * STG_BYTES;
        int kt = s * BK;
        const bf16* Ab = A + (size_t)row0 * K + kt;
        const bf16* Wb = W + (size_t)col0 * K + kt;
#pragma unroll
        for (int i = 0; i < 2; i++) {
            int id = tid + i * 256;
            int r = id >> 2, c = id & 3;
            int cs = c ^ ((r >> 1) & 3);
            cp16(tb + r * 64 + cs * 16, Ab + (size_t)r * K + c * 8);
            cp16(tb + ASTG + r * 64 + cs * 16, Wb + (size_t)r * K + c * 8);
        }
    };

    load_stage(0);
    asm volatile("cp.async.commit_group;\n");
    load_stage(1);
    asm volatile("cp.async.commit_group;\n");

#pragma unroll
    for (int s = 0; s < NS; s++) {
        asm volatile("cp.async.wait_group 1;\n");
        __syncthreads();

        if (s + STAGES - 1 < NS) load_stage(s + STAGES - 1);
        asm volatile("cp.async.commit_group;\n");

        uint32_t stb = sb + (s % STAGES) * STG_BYTES;
#pragma unroll
        for (int kk = 0; kk < 2; kk++) {
            uint32_t c0 = kk * 2;
            uint32_t af[4][4], bq[2][4];
#pragma unroll
            for (int mi = 0; mi < 4; mi++)
                ldsm4(af[mi][0], af[mi][1], af[mi][2], af[mi][3],
                      stb + aoff[mi] + ((((c0 + cA) << 4)) ^ axr[mi]));
#pragma unroll
            for (int p = 0; p < 2; p++)
                ldsm4(bq[p][0], bq[p][1], bq[p][2], bq[p][3],
                      stb + boff[p] + ((((c0 + cB) << 4)) ^ bxr[p]));

#pragma unroll
            for (int mi = 0; mi < 4; mi++)
#pragma unroll
                for (int ni = 0; ni < 4; ni++) {
                    int p = ni >> 1, q = ni & 1;
                    asm volatile(
                        "mma.sync.aligned.m16n8k16.row.col.f32.bf16.bf16.f32 "
                        "{%0,%1,%2,%3}, {%4,%5,%6,%7}, {%8,%9}, {%0,%1,%2,%3};"
                        : "+f"(acc[mi][ni][0]), "+f"(acc[mi][ni][1]),
                          "+f"(acc[mi][ni][2]), "+f"(acc[mi][ni][3])
                        : "r"(af[mi][0]), "r"(af[mi][1]), "r"(af[mi][2]), "r"(af[mi][3]),
                          "r"(bq[p][2 * q]), "r"(bq[p][2 * q + 1]));
                }
        }
    }

#pragma unroll
    for (int mi = 0; mi < 4; mi++) {
#pragma unroll
        for (int ni = 0; ni < 4; ni++) {
            int col = col0 + wn + ni * 8 + 2 * t;
#pragma unroll
            for (int half = 0; half < 2; half++) {
                int row = row0 + wm + mi * 16 + g + half * 8;
                size_t idx = (size_t)row * N + col;
                float v0 = acc[mi][ni][2 * half];
                float v1 = acc[mi][ni][2 * half + 1];
                if (EPI == 0) {
                    *(float2*)&((float*)Cout)[idx] = make_float2(v0, v1);
                } else if (EPI == 2) {
                    float2 bv = *(const float2*)&bias[col];
                    v0 += bv.x; v1 += bv.y;
                    v0 = 0.5f * v0 * (1.f + erff(v0 * 0.7071067811865475f));
                    v1 = 0.5f * v1 * (1.f + erff(v1 * 0.7071067811865475f));
                    __nv_bfloat162 pk;
                    pk.x = __float2bfloat16(v0);
                    pk.y = __float2bfloat16(v1);
                    *(__nv_bfloat162*)&((bf16*)Cout)[idx] = pk;
                } else {
                    float2 bv = *(const float2*)&bias[col];
                    float2 rv = *(const float2*)&res[idx];
                    v0 += bv.x + rv.x; v1 += bv.y + rv.y;
                    *(float2*)&((float*)Cout)[idx] = make_float2(v0, v1);
                }
            }
        }
    }
}

// ---------------------------------------------------------------------------
// Channel attention stage A: per (bh, chunk) partial (k*s)^T v over 112 tokens.
// 144 threads, 4x4 tiles, float4 LDG register prefetch + double-buffered smem
// + nn-PIPELINED LDS (fragments for nn+1 load before nn's FMAs).
// Same loads and per-output fmaf order -> bit-identical.
// ---------------------------------------------------------------------------
#define ATHR 144
#define KVS  56    // padded row stride (floats), 16B aligned
__global__ __launch_bounds__(ATHR, 7)
void attnA_partial(const float* __restrict__ qkv, float* __restrict__ partial)
{
    __shared__ float ks[2][16][KVS];
    __shared__ float vs[2][16][KVS];

    int bh = blockIdx.x;
    int b = bh >> 3, h = bh & 7;
    int chunk = blockIdx.y;
    int nstart = chunk * 112;
    int tid = threadIdx.x;
    int tx = tid % 12, ty = tid / 12;
    const float scale = 0.14433756729740643f;   // 48^-0.5

    const float* base = qkv + (size_t)b * Ntok * H3 + h * HD;

    // static per-thread chunk mapping: slots tid, tid+144, tid+288(<384)
    int nn_s[3], d4_s[3], buf_s[3];
#pragma unroll
    for (int it = 0; it < 3; it++) {
        int idx = tid + it * ATHR;
        int bb2 = idx / 192;
        int rem = idx - bb2 * 192;
        buf_s[it] = bb2;
        nn_s[it]  = rem / 12;
        d4_s[it]  = rem - (rem / 12) * 12;
    }
    bool has2 = (tid < 96);

    float4 pf[3];
    auto prefetch = [&](int n0) {
#pragma unroll
        for (int it = 0; it < 3; it++) {
            if (it == 2 && !has2) break;
            const float* r = base + (size_t)(n0 + nn_s[it]) * H3
                           + (buf_s[it] ? 2 * Cdim : Cdim) + d4_s[it] * 4;
            pf[it] = *(const float4*)r;
        }
    };
    auto store_pf = [&](int sb2) {
#pragma unroll
        for (int it = 0; it < 3; it++) {
            if (it == 2 && !has2) break;
            float4 v4 = pf[it];
            if (buf_s[it] == 0) {
                v4.x *= scale; v4.y *= scale; v4.z *= scale; v4.w *= scale;
                *(float4*)&ks[sb2][nn_s[it]][d4_s[it] * 4] = v4;
            } else {
                *(float4*)&vs[sb2][nn_s[it]][d4_s[it] * 4] = v4;
            }
        }
    };

    float acc[4][4];
#pragma unroll
    for (int i = 0; i < 4; i++)
#pragma unroll
        for (int j = 0; j < 4; j++) acc[i][j] = 0.f;

    prefetch(nstart);
    store_pf(0);
    __syncthreads();

#pragma unroll
    for (int t = 0; t < 7; t++) {
        if (t < 6) prefetch(nstart + (t + 1) * 16);
        int cb = t & 1;

        // nn-pipelined: load fragments for nn+1 before nn's FMAs
        float4 rk = *(const float4*)&ks[cb][0][ty * 4];
        float4 rv = *(const float4*)&vs[cb][0][tx * 4];
#pragma unroll
        for (int nn = 0; nn < 16; nn++) {
            float4 nk, nv;
            if (nn < 15) {
                nk = *(const float4*)&ks[cb][nn + 1][ty * 4];
                nv = *(const float4*)&vs[cb][nn + 1][tx * 4];
            }
            float k[4] = {rk.x, rk.y, rk.z, rk.w};
            float v[4] = {rv.x, rv.y, rv.z, rv.w};
#pragma unroll
            for (int i = 0; i < 4; i++)
#pragma unroll
                for (int j = 0; j < 4; j++)
                    acc[i][j] = fmaf(k[i], v[j], acc[i][j]);
            if (nn < 15) { rk = nk; rv = nv; }
        }
        if (t < 6) store_pf((t + 1) & 1);
        __syncthreads();
    }

    float* o = partial + ((size_t)chunk * (Bsz * NH) + bh) * (HD * HD);
#pragma unroll
    for (int i = 0; i < 4; i++) {
        float4 st = make_float4(acc[i][0], acc[i][1], acc[i][2], acc[i][3]);
        *(float4*)&o[(ty * 4 + i) * HD + tx * 4] = st;
    }
}

// ---------------------------------------------------------------------------
// Fused softmax + attnB, 2-way N split; float4 partial-sum loads.
// Per-element chunk order 0..6 preserved -> bit-identical.
// ---------------------------------------------------------------------------
__global__ __launch_bounds__(384)
void attnBF_kernel(const float* __restrict__ qkv, const float* __restrict__ partial,
                   bf16* __restrict__ out)
{
    __shared__ float at[HD * HD];
    __shared__ float qs[56][HD];

    int bh = blockIdx.x;
    int half = blockIdx.y;
    int b = bh >> 3, h = bh & 7;
    int tid = threadIdx.x;

    // 576 float4 slots; thread t handles t and t+384 (if < 576)
#pragma unroll
    for (int it = 0; it < 2; it++) {
        int idx4 = tid + it * 384;
        if (idx4 < 576) {
            float4 s = make_float4(0.f, 0.f, 0.f, 0.f);
#pragma unroll
            for (int ch = 0; ch < NCHUNK; ch++) {
                const float4 p = *(const float4*)&partial[
                    ((size_t)ch * (Bsz * NH) + bh) * (HD * HD) + idx4 * 4];
                s.x += p.x; s.y += p.y; s.z += p.z; s.w += p.w;
            }
            *(float4*)&at[idx4 * 4] = s;
        }
    }
    __syncthreads();

    if (tid < HD) {
        float* row = &at[tid * HD];
        float m = -1e30f;
#pragma unroll
        for (int e = 0; e < HD; e++) m = fmaxf(m, row[e]);
        float s = 0.f;
#pragma unroll
        for (int e = 0; e < HD; e++) { float tv = expf(row[e] - m); row[e] = tv; s += tv; }
        float inv = 1.f / s;
#pragma unroll
        for (int e = 0; e < HD; e++) row[e] *= inv;
    }
    __syncthreads();

    int nl = tid / HD;
    int d  = tid - nl * HD;
    float4 arow[12];
#pragma unroll
    for (int e4 = 0; e4 < 12; e4++)
        arow[e4] = *(float4*)&at[d * HD + e4 * 4];

    const float* qb = qkv + (size_t)b * Ntok * H3 + h * HD + d;
    bf16* ob = out + (size_t)b * Ntok * Cdim + h * HD + d;

    int nbeg = half * 392;
    for (int n0 = nbeg; n0 < nbeg + 392; n0 += 56) {
#pragma unroll
        for (int r = 0; r < 7; r++)
            qs[nl + 8 * r][d] = qb[(size_t)(n0 + nl + 8 * r) * H3];
        __syncthreads();

        float acc[7] = {0.f, 0.f, 0.f, 0.f, 0.f, 0.f, 0.f};
#pragma unroll
        for (int e4 = 0; e4 < 12; e4++) {
            float4 ar = arow[e4];
#pragma unroll
            for (int r = 0; r < 7; r++) {
                float4 qv = *(float4*)&qs[nl + 8 * r][e4 * 4];
                acc[r] = fmaf(ar.x, qv.x, acc[r]);
                acc[r] = fmaf(ar.y, qv.y, acc[r]);
                acc[r] = fmaf(ar.z, qv.z, acc[r]);
                acc[r] = fmaf(ar.w, qv.w, acc[r]);
            }
        }
#pragma unroll
        for (int r = 0; r < 7; r++)
            ob[(size_t)(n0 + nl + 8 * r) * Cdim] = __float2bfloat16(acc[r]);
        __syncthreads();
    }
}

// ---------------------------------------------------------------------------
// Launch
// ---------------------------------------------------------------------------
extern "C" void kernel_launch(void* const* d_in, const int* in_sizes, int n_in,
                              void* d_out, int out_size)
{
    const float* x       = (const float*)d_in[0];
    const float* cpe0_w  = (const float*)d_in[3];
    const float* cpe0_b  = (const float*)d_in[4];
    const float* cpe1_w  = (const float*)d_in[5];
    const float* cpe1_b  = (const float*)d_in[6];
    const float* norm1_g = (const float*)d_in[7];
    const float* norm1_b = (const float*)d_in[8];
    const float* qkv_w   = (const float*)d_in[9];
    const float* proj_w  = (const float*)d_in[10];
    const float* proj_b  = (const float*)d_in[11];
    const float* norm2_g = (const float*)d_in[12];
    const float* norm2_b = (const float*)d_in[13];
    const float* fc1_w   = (const float*)d_in[14];
    const float* fc1_b   = (const float*)d_in[15];
    const float* fc2_w   = (const float*)d_in[16];
    const float* fc2_b   = (const float*)d_in[17];
    float* out = (float*)d_out;

    float *xa, *qkvb, *attn, *xb;
    bf16 *ln, *att, *hbuf, *wbf;
    cudaGetSymbolAddress((void**)&xa,    g_xa);
    cudaGetSymbolAddress((void**)&ln,    g_ln);
    cudaGetSymbolAddress((void**)&qkvb,  g_qkv);
    cudaGetSymbolAddress((void**)&attn,  g_attn);
    cudaGetSymbolAddress((void**)&att,   g_att);
    cudaGetSymbolAddress((void**)&xb,    g_xb);
    cudaGetSymbolAddress((void**)&hbuf,  g_h);
    cudaGetSymbolAddress((void**)&wbf,   g_wbf);

    cudaFuncSetAttribute(cpe_ln_kernel, cudaFuncAttributeMaxDynamicSharedMemorySize, CPE_SMEM);

    dim3 cpeGrid(4, TJC, Bsz);

    // one launch: convert all weights to bf16
    cvt_all_kernel<<<(W_TOT + 255) / 256, 256>>>(qkv_w, proj_w, fc1_w, fc2_w, wbf);

    // xa = cpe0(x); ln = LN1(xa) [bf16]
    cpe_ln_kernel<<<cpeGrid, Cdim, CPE_SMEM>>>(x, cpe0_w, cpe0_b, norm1_g, norm1_b, xa, ln);
    // qkv = ln1 @ qkv_w^T  (fp32 out)
    gemm_bf16<0, Cdim><<<dim3(H3 / BN, NT / BM), 256>>>(ln, wbf + W_QKV, nullptr, nullptr, qkvb, NT, H3);
    // channel attention
    attnA_partial<<<dim3(Bsz * NH, NCHUNK), ATHR>>>(qkvb, attn);
    attnBF_kernel<<<dim3(Bsz * NH, 2), 384>>>(qkvb, attn, att);
    // xb = xa + att @ proj_w^T + proj_b  (fp32 out)
    gemm_bf16<3, Cdim><<<dim3(Cdim / BN, NT / BM), 256>>>(att, wbf + W_PROJ, proj_b, xa, xb, NT, Cdim);
    // xc = cpe1(xb) -> xa ; ln = LN2(xc) [bf16]
    cpe_ln_kernel<<<cpeGrid, Cdim, CPE_SMEM>>>(xb, cpe1_w, cpe1_b, norm2_g, norm2_b, xa, ln);
    // h = gelu(ln2 @ fc1^T + b1) [bf16 out]
    gemm_bf16<2, Cdim><<<dim3(HID / BN, NT / BM), 256>>>(ln, wbf + W_FC1, fc1_b, nullptr, hbuf, NT, HID);
    // out = xc + h @ fc2^T + b2 (fp32 out)
    gemm_bf16<3, HID><<<dim3(Cdim / BN, NT / BM), 256>>>(hbuf, wbf + W_FC2, fc2_b, xa, out, NT, Cdim);
}